// round 3
// baseline (speedup 1.0000x reference)
#include <cuda_runtime.h>

#define NTOK  4096
#define CDIM  256
#define HIDD  64
#define BATCH 4

// Projection scratch: q,k: [src][b][n][64]; v: [src][b][m][256]
__device__ float g_q[2][BATCH][NTOK][HIDD];
__device__ float g_k[2][BATCH][NTOK][HIDD];
__device__ float g_v[2][BATCH][NTOK][CDIM];

// ---------------------------------------------------------------------------
// Projection: out[o][n] = sum_c W[o][c] * x[b][c][n] + bias[o]
// Combined output rows o in [0,384): [0,64)=q, [64,128)=k, [128,384)=v
// grid (N/64, 6, 2*B), block 256. Each block: 64(o) x 64(n) tile.
// ---------------------------------------------------------------------------
__global__ void proj_kernel(const float* __restrict__ x1, const float* __restrict__ x2,
                            const float* __restrict__ Wq, const float* __restrict__ bq,
                            const float* __restrict__ Wk, const float* __restrict__ bk,
                            const float* __restrict__ Wv, const float* __restrict__ bv)
{
    int ntile = blockIdx.x;
    int otile = blockIdx.y;
    int src   = blockIdx.z >> 2;
    int b     = blockIdx.z & 3;
    const float* x = src ? x2 : x1;

    const float* W; const float* bias; float* outbase; int ostride; int oofs;
    if (otile == 0)      { W = Wq; bias = bq; outbase = &g_q[src][b][0][0]; ostride = HIDD; oofs = 0; }
    else if (otile == 1) { W = Wk; bias = bk; outbase = &g_k[src][b][0][0]; ostride = HIDD; oofs = 0; }
    else                 { W = Wv; bias = bv; outbase = &g_v[src][b][0][0]; ostride = CDIM; oofs = (otile - 2) * 64; }

    __shared__ float Ws[64][65];
    __shared__ float Xs[64][65];

    int t  = threadIdx.x;
    int ty = t >> 4, tx = t & 15;
    float acc[4][4] = {};
    int n0 = ntile * 64;

    for (int cc = 0; cc < CDIM; cc += 64) {
        for (int i = t; i < 64 * 64; i += 256) {
            int r = i >> 6, c = i & 63;
            Ws[r][c] = W[(oofs + r) * CDIM + cc + c];
        }
        for (int i = t; i < 64 * 64; i += 256) {
            int r = i >> 6, c = i & 63;
            Xs[r][c] = x[((size_t)b * CDIM + cc + r) * NTOK + n0 + c];
        }
        __syncthreads();
        #pragma unroll 16
        for (int k = 0; k < 64; k++) {
            float a0 = Ws[ty*4+0][k], a1 = Ws[ty*4+1][k];
            float a2 = Ws[ty*4+2][k], a3 = Ws[ty*4+3][k];
            float b0 = Xs[k][tx*4+0], b1 = Xs[k][tx*4+1];
            float b2 = Xs[k][tx*4+2], b3 = Xs[k][tx*4+3];
            acc[0][0] += a0*b0; acc[0][1] += a0*b1; acc[0][2] += a0*b2; acc[0][3] += a0*b3;
            acc[1][0] += a1*b0; acc[1][1] += a1*b1; acc[1][2] += a1*b2; acc[1][3] += a1*b3;
            acc[2][0] += a2*b0; acc[2][1] += a2*b1; acc[2][2] += a2*b2; acc[2][3] += a2*b3;
            acc[3][0] += a3*b0; acc[3][1] += a3*b1; acc[3][2] += a3*b2; acc[3][3] += a3*b3;
        }
        __syncthreads();
    }

    #pragma unroll
    for (int i = 0; i < 4; i++) {
        int o = oofs + ty * 4 + i;
        float bv_ = bias[o];
        #pragma unroll
        for (int j = 0; j < 4; j++) {
            int n = n0 + tx * 4 + j;
            outbase[(size_t)n * ostride + o] = acc[i][j] + bv_;
        }
    }
}

// ---------------------------------------------------------------------------
// Flash cross-attention.
// grid (N/64, B, 2 dirs), block 256, dynamic smem 116224 B.
// dir0: q=g_q[0], k=g_k[1], v=g_v[1], residual x1 -> out[0]
// dir1: q=g_q[1], k=g_k[0], v=g_v[0], residual x2 -> out[1]
// ---------------------------------------------------------------------------
#define ATTN_SMEM_FLOATS (64*256 + 3*64*65 + 3*64)

__global__ void attn_kernel(const float* __restrict__ x1, const float* __restrict__ x2,
                            const float* __restrict__ gamma_p, float* __restrict__ out)
{
    int qtile = blockIdx.x, b = blockIdx.y, dir = blockIdx.z;
    int srcq = dir, srckv = dir ^ 1;
    const float* xq = dir ? x2 : x1;
    int n0 = qtile * 64;

    extern __shared__ float sm[];
    float* Vs       = sm;                 // 64 x 256 (float4-aligned)
    float* Qs       = Vs + 64 * 256;      // 64 x 65
    float* Ks       = Qs + 64 * 65;       // 64 x 65
    float* Ps       = Ks + 64 * 65;       // 64 x 65
    float* rowmax   = Ps + 64 * 65;       // 64
    float* rowsum   = rowmax + 64;        // 64
    float* rowscale = rowsum + 64;        // 64

    int t = threadIdx.x;
    // S-phase mapping: 4 threads per query row, 16 m-cols each
    int qr = t >> 2, ms = (t & 3) * 16;
    // PV-phase mapping: rows {tq, tq+32}, c range [tc*32, tc*32+32)
    int tq = t & 31, tc = t >> 5;

    const float* qg = &g_q[srcq][b][n0][0];
    for (int i = t; i < 64 * 64; i += 256)
        Qs[(i >> 6) * 65 + (i & 63)] = qg[i];
    if (t < 64) { rowmax[t] = -1e30f; rowsum[t] = 0.f; }
    float accA[32] = {}, accB[32] = {};
    __syncthreads();

    for (int mt = 0; mt < NTOK / 64; mt++) {
        // load K tile (padded) and V tile (float4)
        const float* kg = &g_k[srckv][b][mt * 64][0];
        for (int i = t; i < 64 * 64; i += 256)
            Ks[(i >> 6) * 65 + (i & 63)] = kg[i];
        const float4* vg = (const float4*)&g_v[srckv][b][mt * 64][0];
        float4* Vs4 = (float4*)Vs;
        for (int i = t; i < 64 * 64; i += 256)
            Vs4[i] = vg[i];
        __syncthreads();

        // ---- S = Q K^T for my (row, 16 cols) ----
        float s[16];
        #pragma unroll
        for (int mm = 0; mm < 16; mm++) s[mm] = 0.f;
        const float* qrow = &Qs[qr * 65];
        #pragma unroll
        for (int h0 = 0; h0 < 64; h0 += 4) {
            float q0 = qrow[h0+0], q1 = qrow[h0+1], q2 = qrow[h0+2], q3 = qrow[h0+3];
            #pragma unroll
            for (int mm = 0; mm < 16; mm++) {
                const float* kr = &Ks[(ms + mm) * 65 + h0];
                s[mm] += q0*kr[0] + q1*kr[1] + q2*kr[2] + q3*kr[3];
            }
        }

        // ---- online softmax over this m-tile ----
        float tmax = s[0];
        #pragma unroll
        for (int mm = 1; mm < 16; mm++) tmax = fmaxf(tmax, s[mm]);
        tmax = fmaxf(tmax, __shfl_xor_sync(0xffffffffu, tmax, 1));
        tmax = fmaxf(tmax, __shfl_xor_sync(0xffffffffu, tmax, 2));
        float oldmax = rowmax[qr];
        float newmax = fmaxf(oldmax, tmax);
        float psum = 0.f;
        #pragma unroll
        for (int mm = 0; mm < 16; mm++) {
            float e = __expf(s[mm] - newmax);
            Ps[qr * 65 + ms + mm] = e;
            psum += e;
        }
        psum += __shfl_xor_sync(0xffffffffu, psum, 1);
        psum += __shfl_xor_sync(0xffffffffu, psum, 2);
        if ((t & 3) == 0) {
            float sc = __expf(oldmax - newmax);
            rowscale[qr] = sc;
            rowsum[qr]   = rowsum[qr] * sc + psum;
            rowmax[qr]   = newmax;
        }
        __syncthreads();

        // ---- O = O*scale + P V ----
        float sc0 = rowscale[tq], sc1 = rowscale[tq + 32];
        #pragma unroll
        for (int j = 0; j < 32; j++) { accA[j] *= sc0; accB[j] *= sc1; }
        #pragma unroll 4
        for (int m = 0; m < 64; m++) {
            float p0 = Ps[tq * 65 + m];
            float p1 = Ps[(tq + 32) * 65 + m];
            const float4* vrow = (const float4*)&Vs[m * 256] + tc * 8;
            #pragma unroll
            for (int j4 = 0; j4 < 8; j4++) {
                float4 v = vrow[j4];
                accA[j4*4+0] += p0 * v.x; accA[j4*4+1] += p0 * v.y;
                accA[j4*4+2] += p0 * v.z; accA[j4*4+3] += p0 * v.w;
                accB[j4*4+0] += p1 * v.x; accB[j4*4+1] += p1 * v.y;
                accB[j4*4+2] += p1 * v.z; accB[j4*4+3] += p1 * v.w;
            }
        }
        __syncthreads();
    }

    // normalize, transpose through SMEM (reuse Vs as [c][64]) for coalesced store
    float inv0 = 1.f / rowsum[tq];
    float inv1 = 1.f / rowsum[tq + 32];
    #pragma unroll
    for (int j = 0; j < 32; j++) {
        Vs[(tc * 32 + j) * 64 + tq]      = accA[j] * inv0;
        Vs[(tc * 32 + j) * 64 + tq + 32] = accB[j] * inv1;
    }
    __syncthreads();

    float g = gamma_p[0];
    size_t obase = ((size_t)(dir * BATCH + b)) * CDIM * NTOK;
    const float* xb = xq + (size_t)b * CDIM * NTOK;
    for (int i = t; i < 64 * 256; i += 256) {
        int c = i >> 6, nl = i & 63;
        size_t idx = (size_t)c * NTOK + n0 + nl;
        out[obase + idx] = xb[idx] + g * Vs[c * 64 + nl];
    }
}

extern "C" void kernel_launch(void* const* d_in, const int* in_sizes, int n_in,
                              void* d_out, int out_size)
{
    const float* x1    = (const float*)d_in[0];
    const float* x2    = (const float*)d_in[1];
    const float* Wq    = (const float*)d_in[2];
    const float* bq    = (const float*)d_in[3];
    const float* Wk    = (const float*)d_in[4];
    const float* bk    = (const float*)d_in[5];
    const float* Wv    = (const float*)d_in[6];
    const float* bv    = (const float*)d_in[7];
    const float* gamma = (const float*)d_in[8];
    float* out = (float*)d_out;

    (void)in_sizes; (void)n_in; (void)out_size;

    size_t attn_smem = (size_t)ATTN_SMEM_FLOATS * sizeof(float);
    cudaFuncSetAttribute(attn_kernel, cudaFuncAttributeMaxDynamicSharedMemorySize,
                         (int)attn_smem);

    proj_kernel<<<dim3(NTOK / 64, 6, 2 * BATCH), 256>>>(x1, x2, Wq, bq, Wk, bk, Wv, bv);
    attn_kernel<<<dim3(NTOK / 64, BATCH, 2), 256, attn_smem>>>(x1, x2, gamma, out);
}

// round 6
// speedup vs baseline: 3.4461x; 3.4461x over previous
#include <cuda_runtime.h>
#include <cstdint>

#define NTOK  4096
#define CDIM  256
#define HIDD  64
#define BATCH 4

// Projection scratch (values pre-rounded to tf32): q,k: [src][b][n][64]; v: [src][b][m][256]
__device__ float g_q[2][BATCH][NTOK][HIDD];
__device__ float g_k[2][BATCH][NTOK][HIDD];
__device__ float g_v[2][BATCH][NTOK][CDIM];

// ---------------------------------------------------------------------------
// helpers
// ---------------------------------------------------------------------------
__device__ __forceinline__ float to_tf32(float x) {
    uint32_t u;
    asm("cvt.rna.tf32.f32 %0, %1;" : "=r"(u) : "f"(x));
    return __uint_as_float(u);
}

__device__ __forceinline__ void mma_tf32(float c[4],
                                         uint32_t a0, uint32_t a1, uint32_t a2, uint32_t a3,
                                         uint32_t b0, uint32_t b1) {
    asm volatile(
        "mma.sync.aligned.m16n8k8.row.col.f32.tf32.tf32.f32 "
        "{%0,%1,%2,%3}, {%4,%5,%6,%7}, {%8,%9}, {%0,%1,%2,%3};\n"
        : "+f"(c[0]), "+f"(c[1]), "+f"(c[2]), "+f"(c[3])
        : "r"(a0), "r"(a1), "r"(a2), "r"(a3), "r"(b0), "r"(b1));
}

// fast exp on the FMA pipe (MUFU on B300 is only 0.5/cyc/SM -> too slow for 134M exps)
__device__ __forceinline__ float fexp(float x) {
    float t = x * 1.4426950408889634f;      // log2(e)
    t = fmaxf(t, -126.0f);
    float fi = t + 12582912.0f;             // 1.5 * 2^23 round-to-int magic
    int   ii = __float_as_int(fi) - 0x4B400000;
    float fr = t - (fi - 12582912.0f);      // in [-0.5, 0.5]
    float u  = fr * 0.6931471805599453f;    // ln2
    float p  = 8.3333337e-3f;               // 1/120
    p = fmaf(p, u, 4.1666668e-2f);          // 1/24
    p = fmaf(p, u, 0.16666667f);
    p = fmaf(p, u, 0.5f);
    p = fmaf(p, u, 1.0f);
    p = fmaf(p, u, 1.0f);
    return __int_as_float(__float_as_int(p) + (ii << 23));
}

// ---------------------------------------------------------------------------
// Projection via tf32 mma: out[o][n] = sum_c W[o][c] * x[b][c][n] + bias[o]
// grid (N/64, 6, 2*B), block 256 (8 warps; warp = 16 o-rows x 32 n-cols)
// outputs are tf32-rounded (they only feed mma in the attention kernel)
// ---------------------------------------------------------------------------
__global__ __launch_bounds__(256) void proj_kernel(
    const float* __restrict__ x1, const float* __restrict__ x2,
    const float* __restrict__ Wq, const float* __restrict__ bq,
    const float* __restrict__ Wk, const float* __restrict__ bk,
    const float* __restrict__ Wv, const float* __restrict__ bv)
{
    int ntile = blockIdx.x;
    int otile = blockIdx.y;
    int src   = blockIdx.z >> 2;
    int b     = blockIdx.z & 3;
    const float* x = src ? x2 : x1;

    const float* W; const float* bias; float* outbase; int ostride; int oofs;
    if (otile == 0)      { W = Wq; bias = bq; outbase = &g_q[src][b][0][0]; ostride = HIDD; oofs = 0; }
    else if (otile == 1) { W = Wk; bias = bk; outbase = &g_k[src][b][0][0]; ostride = HIDD; oofs = 0; }
    else                 { W = Wv; bias = bv; outbase = &g_v[src][b][0][0]; ostride = CDIM; oofs = (otile - 2) * 64; }

    __shared__ float Ws[64][68];   // [o][k]
    __shared__ float Xs[64][72];   // [k][n]

    int t    = threadIdx.x;
    int warp = t >> 5, lane = t & 31;
    int g    = lane >> 2, tig = lane & 3;
    int wr   = warp >> 1, wc = warp & 1;
    int n0   = ntile * 64;

    float acc[4][4] = {};

    const float4* W4 = (const float4*)W;

    for (int cc = 0; cc < CDIM; cc += 64) {
        // W tile -> Ws (tf32)
        for (int i = t; i < 1024; i += 256) {
            int r = i >> 4, kq = i & 15;
            float4 w = W4[(size_t)(oofs + r) * 64 + (cc >> 2) + kq];
            Ws[r][kq * 4 + 0] = to_tf32(w.x);
            Ws[r][kq * 4 + 1] = to_tf32(w.y);
            Ws[r][kq * 4 + 2] = to_tf32(w.z);
            Ws[r][kq * 4 + 3] = to_tf32(w.w);
        }
        // X tile -> Xs (tf32)
        const float4* X4 = (const float4*)x;
        for (int i = t; i < 1024; i += 256) {
            int r = i >> 4, cq = i & 15;
            float4 v = X4[(size_t)(b * CDIM + cc + r) * (NTOK / 4) + (n0 >> 2) + cq];
            Xs[r][cq * 4 + 0] = to_tf32(v.x);
            Xs[r][cq * 4 + 1] = to_tf32(v.y);
            Xs[r][cq * 4 + 2] = to_tf32(v.z);
            Xs[r][cq * 4 + 3] = to_tf32(v.w);
        }
        __syncthreads();

        int ob = wr * 16;
        #pragma unroll
        for (int kk = 0; kk < 8; kk++) {
            int k0 = kk * 8;
            uint32_t a0 = __float_as_uint(Ws[ob + g][k0 + tig]);
            uint32_t a1 = __float_as_uint(Ws[ob + g + 8][k0 + tig]);
            uint32_t a2 = __float_as_uint(Ws[ob + g][k0 + tig + 4]);
            uint32_t a3 = __float_as_uint(Ws[ob + g + 8][k0 + tig + 4]);
            #pragma unroll
            for (int j = 0; j < 4; j++) {
                int nb = wc * 32 + j * 8;
                uint32_t b0 = __float_as_uint(Xs[k0 + tig][nb + g]);
                uint32_t b1 = __float_as_uint(Xs[k0 + tig + 4][nb + g]);
                mma_tf32(acc[j], a0, a1, a2, a3, b0, b1);
            }
        }
        __syncthreads();
    }

    // epilogue: bias + tf32 round, transpose to [n][o] staging for coalesced store
    float* stage = &Ws[0][0];   // 64*64 fits in Ws
    {
        int o0 = wr * 16 + g, o1 = o0 + 8;
        float bz0 = bias[oofs + o0], bz1 = bias[oofs + o1];
        #pragma unroll
        for (int j = 0; j < 4; j++) {
            int nl = wc * 32 + j * 8 + tig * 2;
            stage[(nl)     * 64 + o0] = to_tf32(acc[j][0] + bz0);
            stage[(nl + 1) * 64 + o0] = to_tf32(acc[j][1] + bz0);
            stage[(nl)     * 64 + o1] = to_tf32(acc[j][2] + bz1);
            stage[(nl + 1) * 64 + o1] = to_tf32(acc[j][3] + bz1);
        }
    }
    __syncthreads();
    for (int i = t; i < 4096; i += 256) {
        int nl = i >> 6, o = i & 63;
        outbase[(size_t)(n0 + nl) * ostride + oofs + o] = stage[nl * 64 + o];
    }
}

// ---------------------------------------------------------------------------
// Flash cross-attention, tf32 tensor cores.
// grid (N/64, B, 2), block 256 (8 warps).
// Per tile: S = Q K^T (mma), online softmax (fexp), O += P V (mma).
// ---------------------------------------------------------------------------
#define VS_PAD 264
#define QS_PAD 68
#define ATTN_SMEM_FLOATS (64*VS_PAD + 3*64*QS_PAD + 192)

__global__ __launch_bounds__(256) void attn_kernel(
    const float* __restrict__ x1, const float* __restrict__ x2,
    const float* __restrict__ gamma_p, float* __restrict__ out)
{
    int qtile = blockIdx.x, b = blockIdx.y, dir = blockIdx.z;
    int srcq = dir, srckv = dir ^ 1;
    const float* xq = dir ? x2 : x1;
    int n0 = qtile * 64;

    extern __shared__ float sm[];
    float* Vs = sm;                       // 64 x 264 [m][c]
    float* Qs = Vs + 64 * VS_PAD;         // 64 x 68  [q][h]
    float* Ks = Qs + 64 * QS_PAD;         // 64 x 68  [n][h]
    float* Ps = Ks + 64 * QS_PAD;         // 64 x 68  [q][m]
    float* rowmax   = Ps + 64 * QS_PAD;   // 64
    float* rowsum   = rowmax + 64;        // 64
    float* rowscale = rowsum + 64;        // 64

    int t    = threadIdx.x;
    int warp = t >> 5, lane = t & 31;
    int g    = lane >> 2, tig = lane & 3;
    int wr   = warp >> 1, wc = warp & 1;
    int qb   = wr * 16;

    // load Q tile (already tf32)
    {
        const float4* qg4 = (const float4*)&g_q[srcq][b][n0][0];
        for (int i = t; i < 1024; i += 256) {
            int r = i >> 4, cq = i & 15;
            float4 v = qg4[i];
            Qs[r * QS_PAD + cq * 4 + 0] = v.x;
            Qs[r * QS_PAD + cq * 4 + 1] = v.y;
            Qs[r * QS_PAD + cq * 4 + 2] = v.z;
            Qs[r * QS_PAD + cq * 4 + 3] = v.w;
        }
    }
    if (t < 64) { rowmax[t] = -1e30f; rowsum[t] = 0.f; }
    float oacc[16][4] = {};
    __syncthreads();

    for (int mt = 0; mt < NTOK / 64; mt++) {
        // K tile
        {
            const float4* kg4 = (const float4*)&g_k[srckv][b][mt * 64][0];
            for (int i = t; i < 1024; i += 256) {
                int r = i >> 4, cq = i & 15;
                float4 v = kg4[i];
                Ks[r * QS_PAD + cq * 4 + 0] = v.x;
                Ks[r * QS_PAD + cq * 4 + 1] = v.y;
                Ks[r * QS_PAD + cq * 4 + 2] = v.z;
                Ks[r * QS_PAD + cq * 4 + 3] = v.w;
            }
        }
        // V tile
        {
            const float4* vg4 = (const float4*)&g_v[srckv][b][mt * 64][0];
            for (int i = t; i < 4096; i += 256) {
                int r = i >> 6, cq = i & 63;
                float4 v = vg4[i];
                Vs[r * VS_PAD + cq * 4 + 0] = v.x;
                Vs[r * VS_PAD + cq * 4 + 1] = v.y;
                Vs[r * VS_PAD + cq * 4 + 2] = v.z;
                Vs[r * VS_PAD + cq * 4 + 3] = v.w;
            }
        }
        __syncthreads();

        // ---- S = Q K^T : warp computes 16 rows x 32 cols ----
        float sacc[4][4] = {};
        #pragma unroll
        for (int kk = 0; kk < 8; kk++) {
            int k0 = kk * 8;
            uint32_t a0 = __float_as_uint(Qs[(qb + g)     * QS_PAD + k0 + tig]);
            uint32_t a1 = __float_as_uint(Qs[(qb + g + 8) * QS_PAD + k0 + tig]);
            uint32_t a2 = __float_as_uint(Qs[(qb + g)     * QS_PAD + k0 + tig + 4]);
            uint32_t a3 = __float_as_uint(Qs[(qb + g + 8) * QS_PAD + k0 + tig + 4]);
            #pragma unroll
            for (int j = 0; j < 4; j++) {
                int nb = wc * 32 + j * 8;
                uint32_t b0 = __float_as_uint(Ks[(nb + g) * QS_PAD + k0 + tig]);
                uint32_t b1 = __float_as_uint(Ks[(nb + g) * QS_PAD + k0 + tig + 4]);
                mma_tf32(sacc[j], a0, a1, a2, a3, b0, b1);
            }
        }
        // write S to Ps
        #pragma unroll
        for (int j = 0; j < 4; j++) {
            int col = wc * 32 + j * 8 + tig * 2;
            Ps[(qb + g)     * QS_PAD + col]     = sacc[j][0];
            Ps[(qb + g)     * QS_PAD + col + 1] = sacc[j][1];
            Ps[(qb + g + 8) * QS_PAD + col]     = sacc[j][2];
            Ps[(qb + g + 8) * QS_PAD + col + 1] = sacc[j][3];
        }
        __syncthreads();

        // ---- online softmax: 4 threads per row, 16 cols each ----
        {
            int qr = t >> 2, ms = (t & 3) * 16;
            float s[16];
            #pragma unroll
            for (int mm = 0; mm < 16; mm++) s[mm] = Ps[qr * QS_PAD + ms + mm];
            float tmax = s[0];
            #pragma unroll
            for (int mm = 1; mm < 16; mm++) tmax = fmaxf(tmax, s[mm]);
            tmax = fmaxf(tmax, __shfl_xor_sync(0xffffffffu, tmax, 1));
            tmax = fmaxf(tmax, __shfl_xor_sync(0xffffffffu, tmax, 2));
            float oldmax = rowmax[qr];
            float newmax = fmaxf(oldmax, tmax);
            float psum = 0.f;
            #pragma unroll
            for (int mm = 0; mm < 16; mm++) {
                float e = fexp(s[mm] - newmax);
                Ps[qr * QS_PAD + ms + mm] = to_tf32(e);
                psum += e;
            }
            psum += __shfl_xor_sync(0xffffffffu, psum, 1);
            psum += __shfl_xor_sync(0xffffffffu, psum, 2);
            if ((t & 3) == 0) {
                float sc = fexp(oldmax - newmax);
                rowscale[qr] = sc;
                rowsum[qr]   = rowsum[qr] * sc + psum;
                rowmax[qr]   = newmax;
            }
        }
        __syncthreads();

        // ---- O = O*scale + P V : warp computes 16 rows x 128 cols ----
        {
            float sc0 = rowscale[qb + g], sc1 = rowscale[qb + g + 8];
            #pragma unroll
            for (int j = 0; j < 16; j++) {
                oacc[j][0] *= sc0; oacc[j][1] *= sc0;
                oacc[j][2] *= sc1; oacc[j][3] *= sc1;
            }
            #pragma unroll
            for (int kk = 0; kk < 8; kk++) {
                int k0 = kk * 8;
                uint32_t a0 = __float_as_uint(Ps[(qb + g)     * QS_PAD + k0 + tig]);
                uint32_t a1 = __float_as_uint(Ps[(qb + g + 8) * QS_PAD + k0 + tig]);
                uint32_t a2 = __float_as_uint(Ps[(qb + g)     * QS_PAD + k0 + tig + 4]);
                uint32_t a3 = __float_as_uint(Ps[(qb + g + 8) * QS_PAD + k0 + tig + 4]);
                #pragma unroll
                for (int j = 0; j < 16; j++) {
                    int cb = wc * 128 + j * 8;
                    uint32_t b0 = __float_as_uint(Vs[(k0 + tig)     * VS_PAD + cb + g]);
                    uint32_t b1 = __float_as_uint(Vs[(k0 + tig + 4) * VS_PAD + cb + g]);
                    mma_tf32(oacc[j], a0, a1, a2, a3, b0, b1);
                }
            }
        }
        __syncthreads();
    }

    // normalize + transpose to [c][q] staging (reuse Vs) for coalesced output
    {
        float inv0 = 1.f / rowsum[qb + g];
        float inv1 = 1.f / rowsum[qb + g + 8];
        float* stage = Vs;
        #pragma unroll
        for (int j = 0; j < 16; j++) {
            int c = wc * 128 + j * 8 + tig * 2;
            stage[(c)     * 64 + qb + g]     = oacc[j][0] * inv0;
            stage[(c + 1) * 64 + qb + g]     = oacc[j][1] * inv0;
            stage[(c)     * 64 + qb + g + 8] = oacc[j][2] * inv1;
            stage[(c + 1) * 64 + qb + g + 8] = oacc[j][3] * inv1;
        }
    }
    __syncthreads();

    float gm = gamma_p[0];
    size_t obase = ((size_t)(dir * BATCH + b)) * CDIM * NTOK;
    const float* xb = xq + (size_t)b * CDIM * NTOK;
    for (int i = t; i < 64 * 256; i += 256) {
        int c = i >> 6, nl = i & 63;
        size_t idx = (size_t)c * NTOK + n0 + nl;
        out[obase + idx] = xb[idx] + gm * Vs[c * 64 + nl];
    }
}

extern "C" void kernel_launch(void* const* d_in, const int* in_sizes, int n_in,
                              void* d_out, int out_size)
{
    const float* x1    = (const float*)d_in[0];
    const float* x2    = (const float*)d_in[1];
    const float* Wq    = (const float*)d_in[2];
    const float* bq    = (const float*)d_in[3];
    const float* Wk    = (const float*)d_in[4];
    const float* bk    = (const float*)d_in[5];
    const float* Wv    = (const float*)d_in[6];
    const float* bv    = (const float*)d_in[7];
    const float* gamma = (const float*)d_in[8];
    float* out = (float*)d_out;

    (void)in_sizes; (void)n_in; (void)out_size;

    size_t attn_smem = (size_t)ATTN_SMEM_FLOATS * sizeof(float);
    cudaFuncSetAttribute(attn_kernel, cudaFuncAttributeMaxDynamicSharedMemorySize,
                         (int)attn_smem);

    proj_kernel<<<dim3(NTOK / 64, 6, 2 * BATCH), 256>>>(x1, x2, Wq, bq, Wk, bk, Wv, bv);
    attn_kernel<<<dim3(NTOK / 64, BATCH, 2), 256, attn_smem>>>(x1, x2, gamma, out);
}